// round 8
// baseline (speedup 1.0000x reference)
#include <cuda_runtime.h>
#include <cstdint>

// BinaryConv2d: x (8,16,1024,1024) f32, weight (16,16,3,3) in {0,1} -> +/-1
// stride (2,2), pad (1,1) -> out (8,16,512,512)
//
// R8 = R7 + dual-pipe sign application:
//   oc-pairs 0..3 : acc += x * (+/-1)          FFMA2  (fma pipe, rt3: 3 src pairs)
//   oc-pairs 4..7 : acc += (x ^ signmask)      LOP3x2 (alu pipe) + FADD2 (fma, rt2)
// Sign masks stored as +/-0.0f in shared; XOR of sign bit == exact negation.

#define N_BATCH 8
#define C_IN    16
#define C_OUT   16
#define IN_HW   1024
#define OUT_HW  512

#define TH 16              // output rows per block (4 per warp)
#define TW 32              // output cols per block
#define NTHREADS 128

__device__ __forceinline__ unsigned long long bcast2(float x) {
    unsigned long long r;
    asm("mov.b64 %0, {%1, %1};" : "=l"(r) : "f"(x));
    return r;
}

__device__ __forceinline__ void ffma2(unsigned long long& acc,
                                      unsigned long long a,
                                      unsigned long long b) {
    asm("fma.rn.f32x2 %0, %1, %2, %0;" : "+l"(acc) : "l"(a), "l"(b));
}

__device__ __forceinline__ void fadd2(unsigned long long& acc,
                                      unsigned long long a) {
    asm("add.rn.f32x2 %0, %0, %1;" : "+l"(acc) : "l"(a));
}

__device__ __forceinline__ float2 unpack2(unsigned long long v) {
    float2 f;
    asm("mov.b64 {%0, %1}, %2;" : "=f"(f.x), "=f"(f.y) : "l"(v));
    return f;
}

__device__ __forceinline__ void prefetch_l1(const float* p) {
    asm volatile("prefetch.global.L1 [%0];" :: "l"(p));
}

__global__ void __launch_bounds__(NTHREADS, 4)
binconv_kernel(const float* __restrict__ x,
               const float* __restrict__ w,
               float* __restrict__ out) {
    // [c][tap][oc]; oc 0..7 consumed as +/-1.0f (FFMA2 path),
    // oc 8..15 consumed as +/-0.0f sign masks (XOR+FADD2 path).
    __shared__ __align__(16) float s_tab[C_IN * 9 * C_OUT];

    const int tid  = threadIdx.x;
    const int wrp  = tid >> 5;
    const int lane = tid & 31;
    const int tx   = lane & 7;          // x-group (4 output px)
    const int ty   = (lane >> 3) & 3;   // output row within warp band

    const int n  = blockIdx.z;
    const int y0 = blockIdx.y * TH;
    const int x0 = blockIdx.x * TW;

    // ---- decode weights: floats for oc 0..7, sign masks (+/-0.0f) for 8..15 ----
    #pragma unroll
    for (int idx = tid; idx < C_OUT * C_IN * 9; idx += NTHREADS) {
        int oc  = idx / (C_IN * 9);
        int rem = idx - oc * (C_IN * 9);          // c*9 + tap
        bool pos = (w[idx] == 1.0f);
        float v = (oc < 8) ? (pos ? 1.0f : -1.0f)
                           : (pos ? 0.0f : -0.0f);
        s_tab[rem * C_OUT + oc] = v;
    }
    __syncthreads();

    // ---- per-thread input geometry (channel-invariant) ----
    const int oy  = y0 + 4 * wrp + ty;
    const int iy0 = 2 * oy - 1;                   // input row for tap r=0
    const int gxA = 2 * x0 + 8 * tx;              // aligned col of A.x
    const bool eldg = (tx == 0) && (gxA > 0);

    const float* xn = x + ((size_t)n << 24);
    const float* pbase = xn + (ptrdiff_t)iy0 * IN_HW + gxA;

    bool rok[3];
    #pragma unroll
    for (int r = 0; r < 3; ++r)
        rok[r] = (iy0 + r) >= 0;

    // accumulators: [oc_pair 0..7][px 0..3] packed f32x2
    unsigned long long acc[8][4];
    #pragma unroll
    for (int i = 0; i < 8; ++i)
        #pragma unroll
        for (int p = 0; p < 4; ++p)
            acc[i][p] = 0ull;

    // warm L1 for channel 0
    #pragma unroll
    for (int r = 0; r < 3; ++r)
        if (rok[r]) prefetch_l1(pbase + r * IN_HW);

    #pragma unroll 1
    for (int c = 0; c < C_IN; ++c) {
        const float* pc = pbase + ((size_t)c << 20);
        const float* tab_c = s_tab + c * 9 * C_OUT;

        // prefetch next channel's rows (register-free lookahead)
        if (c + 1 < C_IN) {
            const float* pn = pc + (1 << 20);
            #pragma unroll
            for (int r = 0; r < 3; ++r)
                if (rok[r]) prefetch_l1(pn + r * IN_HW);
        }

        #pragma unroll
        for (int r = 0; r < 3; ++r) {
            const float* rp = pc + r * IN_HW;
            float4 A = make_float4(0.f, 0.f, 0.f, 0.f);
            float4 B = make_float4(0.f, 0.f, 0.f, 0.f);
            float  e = 0.f;
            if (rok[r]) {
                A = *(const float4*)rp;           // cols 0..3
                B = *(const float4*)(rp + 4);     // cols 4..7
            }
            if (eldg && rok[r]) e = rp[-1];

            float nb = __shfl_up_sync(0xffffffffu, B.w, 1);
            float xm1 = (tx == 0) ? e : nb;

            unsigned long long xv[9];
            xv[0] = bcast2(xm1);
            xv[1] = bcast2(A.x); xv[2] = bcast2(A.y);
            xv[3] = bcast2(A.z); xv[4] = bcast2(A.w);
            xv[5] = bcast2(B.x); xv[6] = bcast2(B.y);
            xv[7] = bcast2(B.z); xv[8] = bcast2(B.w);

            #pragma unroll
            for (int j = 0; j < 3; ++j) {
                const float* tp = tab_c + (r * 3 + j) * C_OUT;
                // oc-pairs 0..3: +/-1.0 floats (FFMA2 path)
                ulonglong2 s01 = *(const ulonglong2*)(tp);
                ulonglong2 s23 = *(const ulonglong2*)(tp + 4);
                // oc-pairs 4..7: +/-0.0 sign masks (XOR+FADD2 path)
                ulonglong2 m45 = *(const ulonglong2*)(tp + 8);
                ulonglong2 m67 = *(const ulonglong2*)(tp + 12);

                #pragma unroll
                for (int p = 0; p < 4; ++p) {
                    unsigned long long xvp = xv[2 * p + j];
                    // fma pipe (rt3 each)
                    ffma2(acc[0][p], xvp, s01.x);
                    ffma2(acc[1][p], xvp, s01.y);
                    ffma2(acc[2][p], xvp, s23.x);
                    ffma2(acc[3][p], xvp, s23.y);
                    // alu pipe XOR (2x LOP3) + fma pipe FADD2 (rt2)
                    fadd2(acc[4][p], xvp ^ m45.x);
                    fadd2(acc[5][p], xvp ^ m45.y);
                    fadd2(acc[6][p], xvp ^ m67.x);
                    fadd2(acc[7][p], xvp ^ m67.y);
                }
            }
        }
    }

    // ---- writeout: 16 oc x 4 consecutive x -> float4 per oc ----
    const int ox = x0 + 4 * tx;
    float* ob = out + (((size_t)n * C_OUT) * OUT_HW + oy) * OUT_HW + ox;

    #pragma unroll
    for (int i = 0; i < 8; ++i) {
        float2 f0 = unpack2(acc[i][0]);
        float2 f1 = unpack2(acc[i][1]);
        float2 f2 = unpack2(acc[i][2]);
        float2 f3 = unpack2(acc[i][3]);
        float4 lo = make_float4(f0.x, f1.x, f2.x, f3.x);
        float4 hi = make_float4(f0.y, f1.y, f2.y, f3.y);
        *(float4*)(ob + (size_t)(2 * i)     * OUT_HW * OUT_HW) = lo;
        *(float4*)(ob + (size_t)(2 * i + 1) * OUT_HW * OUT_HW) = hi;
    }
}

extern "C" void kernel_launch(void* const* d_in, const int* in_sizes, int n_in,
                              void* d_out, int out_size) {
    const float* x = (const float*)d_in[0];
    const float* w = (const float*)d_in[1];
    float* out = (float*)d_out;

    dim3 grid(OUT_HW / TW, OUT_HW / TH, N_BATCH);   // (16, 32, 8)
    dim3 block(NTHREADS);
    binconv_kernel<<<grid, block>>>(x, w, out);
}

// round 9
// speedup vs baseline: 1.1724x; 1.1724x over previous
#include <cuda_runtime.h>
#include <cstdint>

// BinaryConv2d: x (8,16,1024,1024) f32, weight (16,16,3,3) in {0,1} -> +/-1
// stride (2,2), pad (1,1) -> out (8,16,512,512)
//
// R9 = R7 (direct LDG, shuffle edge, FFMA2 oc-pair accumulators) +
// cross-channel software pipelining: row r of channel c+1 is loaded into a
// second register buffer while row r of channel c is computed. Double-buffer
// roles swap via 2x-unrolled channel loop (no copies). No prefetch insts.

#define N_BATCH 8
#define C_IN    16
#define C_OUT   16
#define IN_HW   1024
#define OUT_HW  512

#define TH 16              // output rows per block (4 per warp)
#define TW 32              // output cols per block
#define NTHREADS 128

__device__ __forceinline__ unsigned long long bcast2(float x) {
    unsigned long long r;
    asm("mov.b64 %0, {%1, %1};" : "=l"(r) : "f"(x));
    return r;
}

__device__ __forceinline__ void ffma2(unsigned long long& acc,
                                      unsigned long long a,
                                      unsigned long long b) {
    asm("fma.rn.f32x2 %0, %1, %2, %0;" : "+l"(acc) : "l"(a), "l"(b));
}

__device__ __forceinline__ float2 unpack2(unsigned long long v) {
    float2 f;
    asm("mov.b64 {%0, %1}, %2;" : "=f"(f.x), "=f"(f.y) : "l"(v));
    return f;
}

struct Rows {
    float4 A[3];
    float4 B[3];
    float  E[3];
};

__global__ void __launch_bounds__(NTHREADS, 3)
binconv_kernel(const float* __restrict__ x,
               const float* __restrict__ w,
               float* __restrict__ out) {
    __shared__ __align__(16) float s_sgn[C_IN * 9 * C_OUT];   // [c][tap][oc]

    const int tid  = threadIdx.x;
    const int wrp  = tid >> 5;
    const int lane = tid & 31;
    const int tx   = lane & 7;          // x-group (4 output px)
    const int ty   = (lane >> 3) & 3;   // output row within warp band

    const int n  = blockIdx.z;
    const int y0 = blockIdx.y * TH;
    const int x0 = blockIdx.x * TW;

    // ---- decode weights into shared sign table (oc fastest) ----
    #pragma unroll
    for (int idx = tid; idx < C_OUT * C_IN * 9; idx += NTHREADS) {
        int oc  = idx / (C_IN * 9);
        int rem = idx - oc * (C_IN * 9);          // c*9 + tap
        s_sgn[rem * C_OUT + oc] = (w[idx] == 1.0f) ? 1.0f : -1.0f;
    }
    __syncthreads();

    // ---- per-thread input geometry (channel-invariant) ----
    const int oy  = y0 + 4 * wrp + ty;
    const int iy0 = 2 * oy - 1;                   // input row for tap r=0
    const int gxA = 2 * x0 + 8 * tx;              // aligned col of A.x
    const bool eldg = (tx == 0) && (gxA > 0);

    const float* xn = x + ((size_t)n << 24);
    const float* pbase = xn + (ptrdiff_t)iy0 * IN_HW + gxA;

    bool rok[3];
    #pragma unroll
    for (int r = 0; r < 3; ++r)
        rok[r] = (iy0 + r) >= 0;                  // only top row can be OOB

    // accumulators: [oc_pair 0..7][px 0..3] packed f32x2
    unsigned long long acc[8][4];
    #pragma unroll
    for (int i = 0; i < 8; ++i)
        #pragma unroll
        for (int p = 0; p < 4; ++p)
            acc[i][p] = 0ull;

    // ---- load one row of one channel into buffer slot r ----
    auto load_row = [&](Rows& R, const float* pc, int r) {
        const float* rp = pc + r * IN_HW;
        R.A[r] = make_float4(0.f, 0.f, 0.f, 0.f);
        R.B[r] = make_float4(0.f, 0.f, 0.f, 0.f);
        R.E[r] = 0.f;
        if (rok[r]) {
            R.A[r] = *(const float4*)rp;          // cols 0..3 (16B aligned)
            R.B[r] = *(const float4*)(rp + 4);    // cols 4..7
            if (eldg) R.E[r] = rp[-1];
        }
    };

    // ---- compute channel c from cur; load channel c+1 rows into nxt ----
    auto step = [&](Rows& cur, Rows& nxt, int c) {
        const float* sgn_c = s_sgn + c * 9 * C_OUT;
        const float* pn = pbase + ((size_t)(c + 1) << 20);
        const bool ld = (c + 1 < C_IN);

        #pragma unroll
        for (int r = 0; r < 3; ++r) {
            if (ld) load_row(nxt, pn, r);         // hidden under this row's FFMA2s

            float nb = __shfl_up_sync(0xffffffffu, cur.B[r].w, 1);
            float xm1 = (tx == 0) ? cur.E[r] : nb;

            unsigned long long xv[9];
            xv[0] = bcast2(xm1);
            xv[1] = bcast2(cur.A[r].x); xv[2] = bcast2(cur.A[r].y);
            xv[3] = bcast2(cur.A[r].z); xv[4] = bcast2(cur.A[r].w);
            xv[5] = bcast2(cur.B[r].x); xv[6] = bcast2(cur.B[r].y);
            xv[7] = bcast2(cur.B[r].z); xv[8] = bcast2(cur.B[r].w);

            #pragma unroll
            for (int j = 0; j < 3; ++j) {
                const ulonglong2* sp =
                    (const ulonglong2*)(sgn_c + (r * 3 + j) * C_OUT);
                ulonglong2 s0 = sp[0];   // broadcast LDS.128, conflict-free
                ulonglong2 s1 = sp[1];
                ulonglong2 s2 = sp[2];
                ulonglong2 s3 = sp[3];
                unsigned long long sv[8] =
                    { s0.x, s0.y, s1.x, s1.y, s2.x, s2.y, s3.x, s3.y };

                #pragma unroll
                for (int p = 0; p < 4; ++p) {
                    unsigned long long xvp = xv[2 * p + j];
                    #pragma unroll
                    for (int i = 0; i < 8; ++i)
                        ffma2(acc[i][p], xvp, sv[i]);
                }
            }
        }
    };

    // ---- prologue: load channel 0; then 2x-unrolled pipelined loop ----
    Rows bufA, bufB;
    #pragma unroll
    for (int r = 0; r < 3; ++r)
        load_row(bufA, pbase, r);

    #pragma unroll 1
    for (int c = 0; c < C_IN; c += 2) {
        step(bufA, bufB, c);        // compute c,   load c+1
        step(bufB, bufA, c + 1);    // compute c+1, load c+2
    }

    // ---- writeout: 16 oc x 4 consecutive x -> float4 per oc ----
    const int ox = x0 + 4 * tx;
    float* ob = out + (((size_t)n * C_OUT) * OUT_HW + oy) * OUT_HW + ox;

    #pragma unroll
    for (int i = 0; i < 8; ++i) {
        float2 f0 = unpack2(acc[i][0]);
        float2 f1 = unpack2(acc[i][1]);
        float2 f2 = unpack2(acc[i][2]);
        float2 f3 = unpack2(acc[i][3]);
        float4 lo = make_float4(f0.x, f1.x, f2.x, f3.x);
        float4 hi = make_float4(f0.y, f1.y, f2.y, f3.y);
        *(float4*)(ob + (size_t)(2 * i)     * OUT_HW * OUT_HW) = lo;
        *(float4*)(ob + (size_t)(2 * i + 1) * OUT_HW * OUT_HW) = hi;
    }
}

extern "C" void kernel_launch(void* const* d_in, const int* in_sizes, int n_in,
                              void* d_out, int out_size) {
    const float* x = (const float*)d_in[0];
    const float* w = (const float*)d_in[1];
    float* out = (float*)d_out;

    dim3 grid(OUT_HW / TW, OUT_HW / TH, N_BATCH);   // (16, 32, 8)
    dim3 block(NTHREADS);
    binconv_kernel<<<grid, block>>>(x, w, out);
}

// round 11
// speedup vs baseline: 1.3940x; 1.1890x over previous
#include <cuda_runtime.h>
#include <cuda_bf16.h>
#include <cstdint>

// BinaryConv2d via warp-level HMMA implicit GEMM (mma.sync m16n8k16 bf16).
// out(n,oc,oy,ox) = sum_{c,r,j} x(n,c,2oy-1+r,2ox-1+j) * sign(oc,c,r,j)
//
// Per mma: D[16oc x 8px] += A[16oc x 16c] * B[16c x 8px], one (r,j) tap,
// one bf16 split of x. 9 taps x 2 splits = 18 accumulating mmas per px-chunk.
// A (signs, bf16 +/-1) lives in registers for the whole kernel (36 regs).
// B read from a staged smem tile: x split into 2 bf16 (exact +/-1 products),
// layout [row(ring3)][physcol][split][c-pair] with 80B col stride and
// even/odd column segregation -> conflict-free LDS.32 B-fragment reads.
//
// Block: 128 thr (4 warps) = 64 output px of one row; 8 rows per block.

#define OUT_HW 512
#define ROWBYTES (129 * 80)      // 129 phys col slots x 80B

__global__ void __launch_bounds__(128)
binconv_mma(const float* __restrict__ x,
            const float* __restrict__ w,
            float* __restrict__ out) {
    __shared__ __align__(16) unsigned char s_x[3 * ROWBYTES];   // 30960 B

    const int tid  = threadIdx.x;
    const int wrp  = tid >> 5;
    const int lane = tid & 31;
    const int g    = lane >> 2;       // fragment group (oc row / px col)
    const int i4   = lane & 3;        // fragment sub-index

    const int n   = blockIdx.z;
    const int x0  = blockIdx.x * 64;  // output px base
    const int oy0 = blockIdx.y * 8;
    const int gx0 = 2 * x0 - 1;       // input col of tile col 0

    const float* xn = x + ((size_t)n << 24);

    // ---- A fragments: signs as bf16 +/-1, held in registers all kernel ----
    // a0=(g,2i) a1=(g+8,2i) a2=(g,2i+8) a3=(g+8,2i+8); k index == channel c.
    uint32_t sA[9][4];
    #pragma unroll
    for (int tap = 0; tap < 9; ++tap) {
        #pragma unroll
        for (int q = 0; q < 4; ++q) {
            int oc = g + (q & 1) * 8;
            int c  = 2 * i4 + (q >> 1) * 8;
            uint32_t lo = (w[oc * 144 + c * 9 + tap]       == 1.f) ? 0x3F80u : 0xBF80u;
            uint32_t hi = (w[oc * 144 + (c + 1) * 9 + tap] == 1.f) ? 0x3F80u : 0xBFu << 8 | 0x80u; // 0xBF80
            sA[tap][q] = lo | (hi << 16);
        }
    }

    // ---- stage one input row (all 16 channels, both bf16 splits) ----
    // thread: channel-pair cp = tid>>4, cols (tid&15) + 16v
    auto stage = [&](int ia) {
        unsigned char* rb = s_x + ((ia + 3) % 3) * ROWBYTES;
        const int cp = tid >> 4;
        const float* p0 = xn + ((size_t)(2 * cp) << 20) + ((size_t)(ia < 0 ? 0 : ia) << 10);
        const float* p1 = p0 + (1 << 20);
        const bool rv = (ia >= 0);
        #pragma unroll
        for (int v = 0; v < 9; ++v) {
            int col = (tid & 15) + 16 * v;
            if (col < 129) {
                int gx = gx0 + col;
                bool ok = rv && ((unsigned)gx < 1024u);
                float a = 0.f, b = 0.f;
                if (ok) { a = p0[gx]; b = p1[gx]; }
                __nv_bfloat16 ah = __float2bfloat16(a);
                __nv_bfloat16 bh = __float2bfloat16(b);
                __nv_bfloat16 al = __float2bfloat16(a - __bfloat162float(ah));
                __nv_bfloat16 bl = __float2bfloat16(b - __bfloat162float(bh));
                int phys = (col >> 1) + (col & 1) * 65;   // even cols 0..64, odd 65..128
                unsigned char* d = rb + phys * 80 + cp * 4;
                *(__nv_bfloat162*)(d)      = __halves2bfloat162(ah, bh);  // split 0
                *(__nv_bfloat162*)(d + 32) = __halves2bfloat162(al, bl);  // split 1
            }
        }
    };

    #pragma unroll 1
    for (int it = 0; it < 8; ++it) {
        const int oy  = oy0 + it;
        const int iy0 = 2 * oy - 1;

        if (it == 0) { stage(iy0); stage(iy0 + 1); stage(iy0 + 2); }
        else         { stage(iy0 + 1); stage(iy0 + 2); }
        __syncthreads();

        const unsigned char* rowb[3];
        #pragma unroll
        for (int r = 0; r < 3; ++r)
            rowb[r] = s_x + ((iy0 + r + 3) % 3) * ROWBYTES;

        float d[2][4];
        #pragma unroll
        for (int nc = 0; nc < 2; ++nc)
            d[nc][0] = d[nc][1] = d[nc][2] = d[nc][3] = 0.f;

        const int pbase = wrp * 16 + g;   // px of this thread's B column (nc=0)

        #pragma unroll
        for (int s = 0; s < 2; ++s) {
            #pragma unroll
            for (int tap = 0; tap < 9; ++tap) {
                const int r  = tap / 3;
                const int j  = tap % 3;
                // col = 2p + j  ->  phys = p + (j>>1) + (j&1)*65
                const int pj = (j == 0) ? 0 : (j == 1) ? 65 : 1;
                const unsigned char* bb =
                    rowb[r] + (size_t)(pbase + pj) * 80 + s * 32 + i4 * 4;
                #pragma unroll
                for (int nc = 0; nc < 2; ++nc) {
                    const unsigned char* ba = bb + nc * (8 * 80);
                    uint32_t b0 = *(const uint32_t*)ba;          // c = 2i,2i+1
                    uint32_t b1 = *(const uint32_t*)(ba + 16);   // c = 2i+8,2i+9
                    asm("mma.sync.aligned.m16n8k16.row.col.f32.bf16.bf16.f32 "
                        "{%0,%1,%2,%3}, {%4,%5,%6,%7}, {%8,%9}, {%0,%1,%2,%3};"
                        : "+f"(d[nc][0]), "+f"(d[nc][1]),
                          "+f"(d[nc][2]), "+f"(d[nc][3])
                        : "r"(sA[tap][0]), "r"(sA[tap][1]),
                          "r"(sA[tap][2]), "r"(sA[tap][3]),
                          "r"(b0), "r"(b1));
                }
            }
        }

        // ---- store: d0,d1 -> oc=g px,px+1 ; d2,d3 -> oc=g+8 ----
        #pragma unroll
        for (int nc = 0; nc < 2; ++nc) {
            int px = x0 + wrp * 16 + nc * 8 + 2 * i4;
            float* o0 = out + (((size_t)(n * 16 + g) * OUT_HW) + oy) * OUT_HW + px;
            float* o1 = o0 + (size_t)8 * OUT_HW * OUT_HW;
            *(float2*)o0 = make_float2(d[nc][0], d[nc][1]);
            *(float2*)o1 = make_float2(d[nc][2], d[nc][3]);
        }
        __syncthreads();   // ring slots reused by next iteration's staging
    }
}

extern "C" void kernel_launch(void* const* d_in, const int* in_sizes, int n_in,
                              void* d_out, int out_size) {
    const float* x = (const float*)d_in[0];
    const float* w = (const float*)d_in[1];
    float* out = (float*)d_out;

    dim3 grid(8, 64, 8);    // 64-px x-tiles, 8-row y-groups, batch
    dim3 block(128);
    binconv_mma<<<grid, block>>>(x, w, out);
}